// round 14
// baseline (speedup 1.0000x reference)
#include <cuda_runtime.h>
#include <cuda_bf16.h>
#include <math.h>
#include <stdint.h>

// Problem constants
#define B_   2
#define S_   2048
#define DIM_ 2048
#define NH_  32
#define NKVH 8
#define QKVO 3072          // (32 + 2*8) * 64
#define KOFF 2048
#define VOFF 2560
#define EPS_ 1e-5f
#define MTOT (B_ * S_)     // 4096

// Scratch (device globals — no allocation allowed)
__device__ float g_qkv[(size_t)B_ * S_ * QKVO];                  // V region used
__device__ __nv_bfloat16 g_ahi[(size_t)MTOT * DIM_];
__device__ __nv_bfloat16 g_alo[(size_t)MTOT * DIM_];
__device__ __nv_bfloat16 g_bhi[(size_t)QKVO * DIM_];
__device__ __nv_bfloat16 g_blo[(size_t)QKVO * DIM_];
// attention operand splits
__device__ __nv_bfloat16 g_qh[(size_t)B_ * NH_ * S_ * 64];
__device__ __nv_bfloat16 g_ql[(size_t)B_ * NH_ * S_ * 64];
__device__ __nv_bfloat16 g_kh[(size_t)B_ * NKVH * S_ * 64];
__device__ __nv_bfloat16 g_kl[(size_t)B_ * NKVH * S_ * 64];
__device__ __nv_bfloat16 g_vh[(size_t)B_ * NKVH * 64 * S_];      // [d][s]
__device__ __nv_bfloat16 g_vl[(size_t)B_ * NKVH * 64 * S_];

// ---------------------------------------------------------------------------
// PTX helpers (sm_103-safe)
// ---------------------------------------------------------------------------
__device__ __forceinline__ uint32_t smem_u32(const void* p) {
    uint32_t a;
    asm("{ .reg .u64 t; cvta.to.shared.u64 t, %1; cvt.u32.u64 %0, t; }"
        : "=r"(a) : "l"(p));
    return a;
}
#define SWZ128(o) ((o) ^ (((o) >> 3) & 0x70))

__device__ __forceinline__ void ldm_x4(uint32_t* r, uint32_t addr) {
    asm volatile("ldmatrix.sync.aligned.m8n8.x4.shared.b16 {%0,%1,%2,%3}, [%4];"
                 : "=r"(r[0]), "=r"(r[1]), "=r"(r[2]), "=r"(r[3]) : "r"(addr));
}
__device__ __forceinline__ void mma_bf16(float* c, const uint32_t* a,
                                         uint32_t b0, uint32_t b1) {
    asm volatile(
        "mma.sync.aligned.m16n8k16.row.col.f32.bf16.bf16.f32 "
        "{%0,%1,%2,%3}, {%4,%5,%6,%7}, {%8,%9}, {%0,%1,%2,%3};"
        : "+f"(c[0]), "+f"(c[1]), "+f"(c[2]), "+f"(c[3])
        : "r"(a[0]), "r"(a[1]), "r"(a[2]), "r"(a[3]), "r"(b0), "r"(b1));
}
__device__ __forceinline__ void cpasync16(uint32_t s, const void* g) {
    asm volatile("cp.async.cg.shared.global [%0], [%1], 16;"
                 :: "r"(s), "l"(g) : "memory");
}
#define CP_COMMIT() asm volatile("cp.async.commit_group;" ::: "memory")
#define CP_WAIT2()  asm volatile("cp.async.wait_group 2;" ::: "memory")
#define CP_WAIT1()  asm volatile("cp.async.wait_group 1;" ::: "memory")
#define CP_WAIT0()  asm volatile("cp.async.wait_group 0;" ::: "memory")

__device__ __forceinline__ void split2(float x, float y,
                                       uint32_t& hi, uint32_t& lo) {
    __nv_bfloat16 hx = __float2bfloat16(x), hy = __float2bfloat16(y);
    __nv_bfloat16 lx = __float2bfloat16(x - __bfloat162float(hx));
    __nv_bfloat16 ly = __float2bfloat16(y - __bfloat162float(hy));
    __nv_bfloat162 H(hx, hy), L(lx, ly);
    hi = *(uint32_t*)&H; lo = *(uint32_t*)&L;
}

// ---------------------------------------------------------------------------
// fp32 -> bf16 hi/lo split (elementwise)
// ---------------------------------------------------------------------------
__global__ __launch_bounds__(256) void convert_split(
    const float* __restrict__ in, __nv_bfloat16* __restrict__ ohi,
    __nv_bfloat16* __restrict__ olo, int n4)
{
    int i = blockIdx.x * 256 + threadIdx.x;
    if (i >= n4) return;
    float4 v = ((const float4*)in)[i];
    uint32_t h0, l0, h1, l1;
    split2(v.x, v.y, h0, l0);
    split2(v.z, v.w, h1, l1);
    uint32_t* H = (uint32_t*)(ohi + (size_t)i * 4);
    uint32_t* L = (uint32_t*)(olo + (size_t)i * 4);
    H[0] = h0; H[1] = h1; L[0] = l0; L[1] = l1;
}

// fp32 [R][C] -> transposed bf16 hi/lo [C][R]
__global__ __launch_bounds__(256) void convert_trans(
    const float* __restrict__ in, __nv_bfloat16* __restrict__ ohi,
    __nv_bfloat16* __restrict__ olo, int R, int C)
{
    __shared__ float t[32][33];
    int bx = blockIdx.x * 32, by = blockIdx.y * 32;
    int lx = threadIdx.x & 31, ly = threadIdx.x >> 5;
#pragma unroll
    for (int i = 0; i < 4; i++)
        t[ly + i * 8][lx] = in[(size_t)(by + ly + i * 8) * C + bx + lx];
    __syncthreads();
#pragma unroll
    for (int i = 0; i < 4; i++) {
        float v = t[lx][ly + i * 8];
        __nv_bfloat16 h = __float2bfloat16(v);
        __nv_bfloat16 l = __float2bfloat16(v - __bfloat162float(h));
        size_t o = (size_t)(bx + ly + i * 8) * R + by + lx;
        ohi[o] = h; olo[o] = l;
    }
}

// ---------------------------------------------------------------------------
// Warp-MMA GEMM v3: C = A * B^T with hi/lo split, 3 products.
// CTA tile 128x128, K-chunk 64, **512 thr / 16 warps, warp tile 32x32**
// (4x4 warp grid) -> ~100 regs/thread, 4 warps/SMSP for latency hiding.
// 2-stage cp.async ring. FUSE=true: fused LayerNorm+RoPE+split epilogue
// (cross-warp LN reduction via smem since a head spans 2 n-warps).
// ---------------------------------------------------------------------------
#define STAGE 65536
#define GSMEM (2 * STAGE)

template <bool FUSE>
__global__ __launch_bounds__(512) void gemm_mma(
    const __nv_bfloat16* __restrict__ Ahi, const __nv_bfloat16* __restrict__ Alo,
    const __nv_bfloat16* __restrict__ Bhi, const __nv_bfloat16* __restrict__ Blo,
    float* __restrict__ C, int N, int K,
    const float* __restrict__ qg, const float* __restrict__ qbeta,
    const float* __restrict__ kg, const float* __restrict__ kbeta,
    const float* __restrict__ fcos, const float* __restrict__ fsin)
{
    extern __shared__ char dyn[];
    const int tid  = threadIdx.x;
    const int wid  = tid >> 5;
    const int lane = tid & 31;
    const int m0 = (wid & 3) * 32;          // 4 m-warps
    const int n0 = (wid >> 2) * 32;         // 4 n-warps
    const int bm = blockIdx.y * 128;
    const int bn = blockIdx.x * 128;
    const uint32_t sbase = smem_u32(dyn);

    float acc[2][4][4];
#pragma unroll
    for (int mi = 0; mi < 2; mi++)
#pragma unroll
        for (int ni = 0; ni < 4; ni++)
#pragma unroll
            for (int q = 0; q < 4; q++) acc[mi][ni][q] = 0.f;

    const int nk = K >> 6;

    auto issue = [&](int ck) {
        const int buf = ck & 1;
        const int k0 = ck * 64;
        const uint32_t sb = sbase + buf * STAGE;
#pragma unroll
        for (int i = 0; i < 2; i++) {
            int u = tid + i * 512;
            int row = u >> 3, c16 = u & 7;
            uint32_t so = SWZ128((uint32_t)(row * 128 + c16 * 16));
            size_t ga = (size_t)(bm + row) * K + k0 + c16 * 8;
            size_t gb = (size_t)(bn + row) * K + k0 + c16 * 8;
            cpasync16(sb +         so, Ahi + ga);
            cpasync16(sb + 16384 + so, Alo + ga);
            cpasync16(sb + 32768 + so, Bhi + gb);
            cpasync16(sb + 49152 + so, Blo + gb);
        }
        CP_COMMIT();
    };

    issue(0);
    const int lrow = lane & 15;
    const int lcb  = (lane >> 4) * 16;

    for (int ck = 0; ck < nk; ck++) {
        if (ck + 1 < nk) { issue(ck + 1); CP_WAIT1(); }
        else             { CP_WAIT0(); }
        __syncthreads();
        const uint32_t sb = sbase + (ck & 1) * STAGE;

#pragma unroll
        for (int kk = 0; kk < 4; kk++) {
            uint32_t ah[2][4], al[2][4], bh[2][4], bl[2][4];
#pragma unroll
            for (int mi = 0; mi < 2; mi++) {
                uint32_t off = SWZ128((uint32_t)((m0 + mi * 16 + lrow) * 128 +
                                                 kk * 32 + lcb));
                ldm_x4(ah[mi], sb + off);
                ldm_x4(al[mi], sb + 16384 + off);
            }
#pragma unroll
            for (int nj = 0; nj < 2; nj++) {
                uint32_t off = SWZ128((uint32_t)((n0 + nj * 16 + lrow) * 128 +
                                                 kk * 32 + lcb));
                ldm_x4(bh[nj], sb + 32768 + off);
                ldm_x4(bl[nj], sb + 49152 + off);
            }
#pragma unroll
            for (int mi = 0; mi < 2; mi++)
#pragma unroll
                for (int ni = 0; ni < 4; ni++) {
                    const uint32_t* bf = bh[ni >> 1];
                    const uint32_t* bg = bl[ni >> 1];
                    uint32_t b0h = (ni & 1) ? bf[1] : bf[0];
                    uint32_t b1h = (ni & 1) ? bf[3] : bf[2];
                    uint32_t b0l = (ni & 1) ? bg[1] : bg[0];
                    uint32_t b1l = (ni & 1) ? bg[3] : bg[2];
                    mma_bf16(acc[mi][ni], ah[mi], b0h, b1h);
                    mma_bf16(acc[mi][ni], ah[mi], b0l, b1l);
                    mma_bf16(acc[mi][ni], al[mi], b0h, b1h);
                }
        }
        __syncthreads();
    }

    // ---------------- epilogue ----------------
    const int g = bn + n0;          // 32-col granularity
    const int hh = g >> 6;          // head index (Q:0-31, K:32-39, V:40-47)
    bool plain = !FUSE || (hh >= 40);

    if (plain) {
#pragma unroll
        for (int mi = 0; mi < 2; mi++) {
            int r0 = bm + m0 + mi * 16 + (lane >> 2);
#pragma unroll
            for (int ni = 0; ni < 4; ni++) {
                int c = g + ni * 8 + (lane & 3) * 2;
                *(float2*)&C[(size_t)r0 * N + c] =
                    make_float2(acc[mi][ni][0], acc[mi][ni][1]);
                *(float2*)&C[(size_t)(r0 + 8) * N + c] =
                    make_float2(acc[mi][ni][2], acc[mi][ni][3]);
            }
        }
    } else {
        const bool isQ = (hh < 32);
        const float* gam = isQ ? qg : kg;
        const float* bet = isQ ? qbeta : kbeta;
        const float scl = isQ ? 0.125f : 1.f;
        __nv_bfloat16* dh = isQ ? g_qh : g_kh;
        __nv_bfloat16* dl = isQ ? g_ql : g_kl;
        const int hloc = isQ ? hh : hh - 32;
        const int nheads = isQ ? NH_ : NKVH;
        const int nw = wid >> 2;
        const int nhalf = n0 & 32;           // head-local column base (0 or 32)
        float* red = (float*)dyn;            // [128 rows][4 nwarps][2] = 4 KB

        // partial LN sums for this thread's rows over its 32-col half
        float ps[2][2], pq[2][2];            // [mi][row-half]
#pragma unroll
        for (int mi = 0; mi < 2; mi++) {
            float s0 = 0.f, q0 = 0.f, s1 = 0.f, q1 = 0.f;
#pragma unroll
            for (int ni = 0; ni < 4; ni++) {
                s0 += acc[mi][ni][0] + acc[mi][ni][1];
                q0 += acc[mi][ni][0] * acc[mi][ni][0] +
                      acc[mi][ni][1] * acc[mi][ni][1];
                s1 += acc[mi][ni][2] + acc[mi][ni][3];
                q1 += acc[mi][ni][2] * acc[mi][ni][2] +
                      acc[mi][ni][3] * acc[mi][ni][3];
            }
#pragma unroll
            for (int off = 1; off <= 2; off <<= 1) {
                s0 += __shfl_xor_sync(0xffffffffu, s0, off);
                q0 += __shfl_xor_sync(0xffffffffu, q0, off);
                s1 += __shfl_xor_sync(0xffffffffu, s1, off);
                q1 += __shfl_xor_sync(0xffffffffu, q1, off);
            }
            ps[mi][0] = s0; pq[mi][0] = q0;
            ps[mi][1] = s1; pq[mi][1] = q1;
            if ((lane & 3) == 0) {
                int r = m0 + mi * 16 + (lane >> 2);
                red[(r)     * 8 + nw * 2 + 0] = s0;
                red[(r)     * 8 + nw * 2 + 1] = q0;
                red[(r + 8) * 8 + nw * 2 + 0] = s1;
                red[(r + 8) * 8 + nw * 2 + 1] = q1;
            }
        }
        __syncthreads();

        const int pw = nw ^ 1;               // partner n-warp (other head half)
#pragma unroll
        for (int mi = 0; mi < 2; mi++) {
            int r = m0 + mi * 16 + (lane >> 2);
            float s0 = ps[mi][0] + red[(r)     * 8 + pw * 2 + 0];
            float q0 = pq[mi][0] + red[(r)     * 8 + pw * 2 + 1];
            float s1 = ps[mi][1] + red[(r + 8) * 8 + pw * 2 + 0];
            float q1 = pq[mi][1] + red[(r + 8) * 8 + pw * 2 + 1];
            float mu0 = s0 * (1.f / 64.f);
            float rs0 = rsqrtf(q0 * (1.f / 64.f) - mu0 * mu0 + EPS_);
            float mu1 = s1 * (1.f / 64.f);
            float rs1 = rsqrtf(q1 * (1.f / 64.f) - mu1 * mu1 + EPS_);

            int r0g = bm + r;
            int r1g = r0g + 8;
            int b0 = r0g >> 11, si0 = r0g & (S_ - 1);
            int b1 = r1g >> 11, si1 = r1g & (S_ - 1);
            size_t base0 = ((size_t)(b0 * nheads + hloc) * S_ + si0) * 64;
            size_t base1 = ((size_t)(b1 * nheads + hloc) * S_ + si1) * 64;

#pragma unroll
            for (int ni = 0; ni < 4; ni++) {
                int cc = nhalf + ni * 8 + (lane & 3) * 2;
                float gm0 = gam[cc], gm1 = gam[cc + 1];
                float bt0 = bet[cc], bt1 = bet[cc + 1];
                int f = cc >> 1;
                {   // row r0g
                    float xr = (acc[mi][ni][0] - mu0) * rs0 * gm0 + bt0;
                    float xi = (acc[mi][ni][1] - mu0) * rs0 * gm1 + bt1;
                    float c_ = fcos[si0 * 32 + f], sn = fsin[si0 * 32 + f];
                    uint32_t hi, lo;
                    split2((xr * c_ - xi * sn) * scl,
                           (xr * sn + xi * c_) * scl, hi, lo);
                    *(uint32_t*)(dh + base0 + cc) = hi;
                    *(uint32_t*)(dl + base0 + cc) = lo;
                }
                {   // row r0g + 8
                    float xr = (acc[mi][ni][2] - mu1) * rs1 * gm0 + bt0;
                    float xi = (acc[mi][ni][3] - mu1) * rs1 * gm1 + bt1;
                    float c_ = fcos[si1 * 32 + f], sn = fsin[si1 * 32 + f];
                    uint32_t hi, lo;
                    split2((xr * c_ - xi * sn) * scl,
                           (xr * sn + xi * c_) * scl, hi, lo);
                    *(uint32_t*)(dh + base1 + cc) = hi;
                    *(uint32_t*)(dl + base1 + cc) = lo;
                }
            }
        }
    }
}

// ---------------------------------------------------------------------------
// V: fp32 [b][s][kvh*64+d] -> bf16 hi/lo transposed [b*8+kvh][d][s]
// ---------------------------------------------------------------------------
__global__ __launch_bounds__(256) void vtrans_kernel()
{
    __shared__ float t[32][33];
    int s0 = blockIdx.x * 32;
    int d0 = blockIdx.y * 32;
    int bz = blockIdx.z;
    int b = bz >> 3, kvh = bz & 7;
    int lx = threadIdx.x & 31, ly = threadIdx.x >> 5;
#pragma unroll
    for (int i = 0; i < 4; i++)
        t[ly + i * 8][lx] =
            g_qkv[(size_t)(b * S_ + s0 + ly + i * 8) * QKVO + VOFF + kvh * 64 + d0 + lx];
    __syncthreads();
#pragma unroll
    for (int i = 0; i < 4; i++) {
        float v = t[lx][ly + i * 8];
        __nv_bfloat16 h = __float2bfloat16(v);
        __nv_bfloat16 l = __float2bfloat16(v - __bfloat162float(h));
        size_t o = ((size_t)bz * 64 + d0 + ly + i * 8) * S_ + s0 + lx;
        g_vh[o] = h; g_vl[o] = l;
    }
}

// ---------------------------------------------------------------------------
// Tensor-core flash attention (round-7 proven config): 256 thr / 8 warps,
// Q tile 128 (16 rows/warp), K tile 64, 3-stage cp.async ring.
// Writes output directly as bf16 hi/lo splits into gemm2's A buffers.
// ---------------------------------------------------------------------------
#define ATT_STAGE 32768                        // Kh|Kl|Vh|Vl, 8 KB each
#define ATT_SMEM (3 * ATT_STAGE + 32768)       // + Qh|Ql (16 KB each) = 128 KB

__global__ __launch_bounds__(256) void attn_mma()
{
    extern __shared__ char dyn[];
    const int tid = threadIdx.x, wid = tid >> 5, lane = tid & 31;
    const int b = blockIdx.z, h = blockIdx.y;
    const int qb = (int)gridDim.x - 1 - (int)blockIdx.x;   // heavy first
    const int kvh = h >> 2;
    const uint32_t sb = smem_u32(dyn);
    const uint32_t qsm = sb + 3 * ATT_STAGE;

    const __nv_bfloat16* Qh = g_qh + ((size_t)(b * NH_ + h) * S_ + qb * 128) * 64;
    const __nv_bfloat16* Ql = g_ql + ((size_t)(b * NH_ + h) * S_ + qb * 128) * 64;
    const __nv_bfloat16* Kh = g_kh + (size_t)(b * NKVH + kvh) * S_ * 64;
    const __nv_bfloat16* Kl = g_kl + (size_t)(b * NKVH + kvh) * S_ * 64;
    const __nv_bfloat16* Vh = g_vh + (size_t)(b * NKVH + kvh) * 64 * S_;
    const __nv_bfloat16* Vl = g_vl + (size_t)(b * NKVH + kvh) * 64 * S_;

    const int nkb = 2 * qb + 2;

    auto issueKV = [&](int kb) {
        uint32_t st = sb + (kb % 3) * ATT_STAGE;
        const __nv_bfloat16* kh = Kh + (size_t)kb * 64 * 64;
        const __nv_bfloat16* kl = Kl + (size_t)kb * 64 * 64;
        const __nv_bfloat16* vh = Vh + kb * 64;
        const __nv_bfloat16* vl = Vl + kb * 64;
#pragma unroll
        for (int i = 0; i < 2; i++) {
            int u = tid + i * 256;
            int row = u >> 3, c16 = u & 7;
            uint32_t so = SWZ128((uint32_t)(row * 128 + c16 * 16));
            cpasync16(st +         so, kh + row * 64 + c16 * 8);
            cpasync16(st +  8192 + so, kl + row * 64 + c16 * 8);
            cpasync16(st + 16384 + so, vh + (size_t)row * S_ + c16 * 8);
            cpasync16(st + 24576 + so, vl + (size_t)row * S_ + c16 * 8);
        }
        CP_COMMIT();
    };

    // Q tile loads (group 0, committed by issueKV(0))
#pragma unroll
    for (int i = 0; i < 4; i++) {
        int u = tid + i * 256;
        int row = u >> 3, c16 = u & 7;
        uint32_t so = SWZ128((uint32_t)(row * 128 + c16 * 16));
        cpasync16(qsm +         so, Qh + (size_t)row * 64 + c16 * 8);
        cpasync16(qsm + 16384 + so, Ql + (size_t)row * 64 + c16 * 8);
    }
    issueKV(0);
    if (nkb > 1) issueKV(1);

    const int lrow = lane & 15;
    const int lcb  = (lane >> 4) * 16;

    uint32_t qfh[4][4], qfl[4][4];
    float o[8][4];
#pragma unroll
    for (int j = 0; j < 8; j++)
#pragma unroll
        for (int c = 0; c < 4; c++) o[j][c] = 0.f;
    float m0 = -1e30f, m1 = -1e30f, l0 = 0.f, l1 = 0.f;

    for (int kb = 0; kb < nkb; kb++) {
        __syncthreads();                       // stage reuse guard
        if (kb + 2 < nkb) { issueKV(kb + 2); CP_WAIT2(); }
        else if (kb + 1 < nkb) { CP_WAIT1(); }
        else { CP_WAIT0(); }
        __syncthreads();                       // data visible to all

        if (kb == 0) {
#pragma unroll
            for (int kc = 0; kc < 4; kc++) {
                uint32_t off = SWZ128((uint32_t)((wid * 16 + lrow) * 128 +
                                                 kc * 32 + lcb));
                ldm_x4(qfh[kc], qsm + off);
                ldm_x4(qfl[kc], qsm + 16384 + off);
            }
        }

        const uint32_t st = sb + (kb % 3) * ATT_STAGE;
        const int wrow0 = qb * 128 + wid * 16;
        if (kb * 64 > wrow0 + 15) continue;    // fully masked for this warp

        // ---- S = Q K^T (3-product split) ----
        float sc[8][4];
#pragma unroll
        for (int j = 0; j < 8; j++)
#pragma unroll
            for (int c = 0; c < 4; c++) sc[j][c] = 0.f;
#pragma unroll
        for (int kc = 0; kc < 4; kc++) {
#pragma unroll
            for (int nj = 0; nj < 4; nj++) {
                uint32_t off = SWZ128((uint32_t)((nj * 16 + lrow) * 128 +
                                                 kc * 32 + lcb));
                uint32_t bh[4], bl[4];
                ldm_x4(bh, st + off);
                ldm_x4(bl, st + 8192 + off);
#pragma unroll
                for (int sub = 0; sub < 2; sub++) {
                    int ni = nj * 2 + sub;
                    mma_bf16(sc[ni], qfh[kc], bh[sub], bh[2 + sub]);
                    mma_bf16(sc[ni], qfh[kc], bl[sub], bl[2 + sub]);
                    mma_bf16(sc[ni], qfl[kc], bh[sub], bh[2 + sub]);
                }
            }
        }

        // ---- causal mask ----
        const int gr0 = wrow0 + (lane >> 2);
        if (kb * 64 + 63 > wrow0) {
#pragma unroll
            for (int j = 0; j < 8; j++) {
                int cb = kb * 64 + j * 8 + (lane & 3) * 2;
                if (cb     > gr0)     sc[j][0] = -1e30f;
                if (cb + 1 > gr0)     sc[j][1] = -1e30f;
                if (cb     > gr0 + 8) sc[j][2] = -1e30f;
                if (cb + 1 > gr0 + 8) sc[j][3] = -1e30f;
            }
        }

        // ---- online softmax (fp32, quad reductions) ----
        float mt0 = -1e30f, mt1 = -1e30f;
#pragma unroll
        for (int j = 0; j < 8; j++) {
            mt0 = fmaxf(mt0, fmaxf(sc[j][0], sc[j][1]));
            mt1 = fmaxf(mt1, fmaxf(sc[j][2], sc[j][3]));
        }
#pragma unroll
        for (int off = 1; off <= 2; off <<= 1) {
            mt0 = fmaxf(mt0, __shfl_xor_sync(0xffffffffu, mt0, off));
            mt1 = fmaxf(mt1, __shfl_xor_sync(0xffffffffu, mt1, off));
        }
        float mn0 = fmaxf(m0, mt0), mn1 = fmaxf(m1, mt1);
        float cr0 = __expf(m0 - mn0), cr1 = __expf(m1 - mn1);
        float rs0 = 0.f, rs1 = 0.f;
#pragma unroll
        for (int j = 0; j < 8; j++) {
            sc[j][0] = __expf(sc[j][0] - mn0);
            sc[j][1] = __expf(sc[j][1] - mn0);
            sc[j][2] = __expf(sc[j][2] - mn1);
            sc[j][3] = __expf(sc[j][3] - mn1);
            rs0 += sc[j][0] + sc[j][1];
            rs1 += sc[j][2] + sc[j][3];
        }
#pragma unroll
        for (int off = 1; off <= 2; off <<= 1) {
            rs0 += __shfl_xor_sync(0xffffffffu, rs0, off);
            rs1 += __shfl_xor_sync(0xffffffffu, rs1, off);
        }
        l0 = l0 * cr0 + rs0; l1 = l1 * cr1 + rs1;
        m0 = mn0; m1 = mn1;
#pragma unroll
        for (int j = 0; j < 8; j++) {
            o[j][0] *= cr0; o[j][1] *= cr0;
            o[j][2] *= cr1; o[j][3] *= cr1;
        }

        // ---- PV: split P to bf16 hi/lo A-frags, 3-product mma ----
#pragma unroll
        for (int t = 0; t < 4; t++) {
            uint32_t aph[4], apl[4];
            split2(sc[2 * t][0],     sc[2 * t][1],     aph[0], apl[0]);
            split2(sc[2 * t][2],     sc[2 * t][3],     aph[1], apl[1]);
            split2(sc[2 * t + 1][0], sc[2 * t + 1][1], aph[2], apl[2]);
            split2(sc[2 * t + 1][2], sc[2 * t + 1][3], aph[3], apl[3]);
#pragma unroll
            for (int nj = 0; nj < 4; nj++) {
                uint32_t off = SWZ128((uint32_t)((nj * 16 + lrow) * 128 +
                                                 t * 32 + lcb));
                uint32_t bh[4], bl[4];
                ldm_x4(bh, st + 16384 + off);
                ldm_x4(bl, st + 24576 + off);
#pragma unroll
                for (int sub = 0; sub < 2; sub++) {
                    int ni = nj * 2 + sub;
                    mma_bf16(o[ni], aph, bh[sub], bh[2 + sub]);
                    mma_bf16(o[ni], aph, bl[sub], bl[2 + sub]);
                    mma_bf16(o[ni], apl, bh[sub], bh[2 + sub]);
                }
            }
        }
    }

    // ---- epilogue: write bf16 hi/lo splits directly into gemm2 A ----
    float il0 = 1.f / l0, il1 = 1.f / l1;
    int r0 = qb * 128 + wid * 16 + (lane >> 2);
    size_t row0 = (size_t)(b * S_ + r0) * DIM_;
    size_t row1 = row0 + (size_t)8 * DIM_;
    int colbase = h * 64 + (lane & 3) * 2;
#pragma unroll
    for (int j = 0; j < 8; j++) {
        uint32_t h0, lo0, h1, lo1;
        split2(o[j][0] * il0, o[j][1] * il0, h0, lo0);
        split2(o[j][2] * il1, o[j][3] * il1, h1, lo1);
        int c = colbase + j * 8;
        *(uint32_t*)(g_ahi + row0 + c) = h0;
        *(uint32_t*)(g_alo + row0 + c) = lo0;
        *(uint32_t*)(g_ahi + row1 + c) = h1;
        *(uint32_t*)(g_alo + row1 + c) = lo1;
    }
}

// ---------------------------------------------------------------------------
extern "C" void kernel_launch(void* const* d_in, const int* in_sizes, int n_in,
                              void* d_out, int out_size)
{
    const float* x     = (const float*)d_in[0];
    const float* wqkv  = (const float*)d_in[1];
    const float* wo    = (const float*)d_in[2];
    const float* q_g   = (const float*)d_in[3];
    const float* q_b   = (const float*)d_in[4];
    const float* k_g   = (const float*)d_in[5];
    const float* k_b   = (const float*)d_in[6];
    const float* fcos  = (const float*)d_in[7];
    const float* fsin  = (const float*)d_in[8];
    float* out = (float*)d_out;

    float* qkv_p = nullptr;
    __nv_bfloat16 *ahi, *alo, *bhi, *blo;
    cudaGetSymbolAddress((void**)&qkv_p, g_qkv);
    cudaGetSymbolAddress((void**)&ahi, g_ahi);
    cudaGetSymbolAddress((void**)&alo, g_alo);
    cudaGetSymbolAddress((void**)&bhi, g_bhi);
    cudaGetSymbolAddress((void**)&blo, g_blo);

    cudaFuncSetAttribute(gemm_mma<true>,
                         cudaFuncAttributeMaxDynamicSharedMemorySize, GSMEM);
    cudaFuncSetAttribute(gemm_mma<false>,
                         cudaFuncAttributeMaxDynamicSharedMemorySize, GSMEM);
    cudaFuncSetAttribute(attn_mma,
                         cudaFuncAttributeMaxDynamicSharedMemorySize, ATT_SMEM);

    // 1) split x (1 launch) and wqkv (2 launches -> gemm1 is launch #3 for ncu)
    {
        int n4 = MTOT * DIM_ / 4;
        convert_split<<<(n4 + 255) / 256, 256>>>(x, ahi, alo, n4);
        int half = QKVO * DIM_ / 2;
        int h4 = half / 4;
        convert_split<<<(h4 + 255) / 256, 256>>>(wqkv, bhi, blo, h4);
        convert_split<<<(h4 + 255) / 256, 256>>>(wqkv + half, bhi + half,
                                                 blo + half, h4);
    }

    // 2) QKV projection + fused LayerNorm/RoPE/split epilogue (launch #3)
    {
        dim3 grid(QKVO / 128, MTOT / 128);
        gemm_mma<true><<<grid, 512, GSMEM>>>(ahi, alo, bhi, blo, qkv_p,
                                             QKVO, DIM_, q_g, q_b, k_g, k_b,
                                             fcos, fsin);
    }

    // 3) V transpose/split
    {
        dim3 vg(S_ / 32, 2, B_ * NKVH);
        vtrans_kernel<<<vg, 256>>>();
    }

    // 4) Tensor-core flash attention (writes gemm2 A splits directly)
    {
        dim3 grid(S_ / 128, NH_, B_);
        attn_mma<<<grid, 256, ATT_SMEM>>>();
    }

    // 5) transpose+split wo -> [d][f]
    {
        dim3 tg(DIM_ / 32, DIM_ / 32);
        convert_trans<<<tg, 256>>>(wo, bhi, blo, DIM_, DIM_);
    }

    // 6) Output projection (tensor cores)
    {
        dim3 grid(DIM_ / 128, MTOT / 128);
        gemm_mma<false><<<grid, 512, GSMEM>>>(ahi, alo, bhi, blo, out,
                                              DIM_, DIM_, nullptr, nullptr,
                                              nullptr, nullptr, nullptr, nullptr);
    }
}

// round 15
// speedup vs baseline: 1.0185x; 1.0185x over previous
#include <cuda_runtime.h>
#include <cuda_bf16.h>
#include <math.h>
#include <stdint.h>

// Problem constants
#define B_   2
#define S_   2048
#define DIM_ 2048
#define NH_  32
#define NKVH 8
#define QKVO 3072          // (32 + 2*8) * 64
#define KOFF 2048
#define VOFF 2560
#define EPS_ 1e-5f
#define MTOT (B_ * S_)     // 4096

// Scratch (device globals — no allocation allowed)
__device__ float g_qkv[(size_t)B_ * S_ * QKVO];                  // V region used
__device__ __nv_bfloat16 g_ahi[(size_t)MTOT * DIM_];
__device__ __nv_bfloat16 g_alo[(size_t)MTOT * DIM_];
__device__ __nv_bfloat16 g_bhi[(size_t)QKVO * DIM_];
__device__ __nv_bfloat16 g_blo[(size_t)QKVO * DIM_];
// attention operand splits
__device__ __nv_bfloat16 g_qh[(size_t)B_ * NH_ * S_ * 64];
__device__ __nv_bfloat16 g_ql[(size_t)B_ * NH_ * S_ * 64];
__device__ __nv_bfloat16 g_kh[(size_t)B_ * NKVH * S_ * 64];
__device__ __nv_bfloat16 g_kl[(size_t)B_ * NKVH * S_ * 64];
__device__ __nv_bfloat16 g_vh[(size_t)B_ * NKVH * 64 * S_];      // [d][s]
__device__ __nv_bfloat16 g_vl[(size_t)B_ * NKVH * 64 * S_];

// ---------------------------------------------------------------------------
// PTX helpers (sm_103-safe)
// ---------------------------------------------------------------------------
__device__ __forceinline__ uint32_t smem_u32(const void* p) {
    uint32_t a;
    asm("{ .reg .u64 t; cvta.to.shared.u64 t, %1; cvt.u32.u64 %0, t; }"
        : "=r"(a) : "l"(p));
    return a;
}
#define SWZ128(o) ((o) ^ (((o) >> 3) & 0x70))

__device__ __forceinline__ void ldm_x4(uint32_t* r, uint32_t addr) {
    asm volatile("ldmatrix.sync.aligned.m8n8.x4.shared.b16 {%0,%1,%2,%3}, [%4];"
                 : "=r"(r[0]), "=r"(r[1]), "=r"(r[2]), "=r"(r[3]) : "r"(addr));
}
__device__ __forceinline__ void mma_bf16(float* c, const uint32_t* a,
                                         uint32_t b0, uint32_t b1) {
    asm volatile(
        "mma.sync.aligned.m16n8k16.row.col.f32.bf16.bf16.f32 "
        "{%0,%1,%2,%3}, {%4,%5,%6,%7}, {%8,%9}, {%0,%1,%2,%3};"
        : "+f"(c[0]), "+f"(c[1]), "+f"(c[2]), "+f"(c[3])
        : "r"(a[0]), "r"(a[1]), "r"(a[2]), "r"(a[3]), "r"(b0), "r"(b1));
}
__device__ __forceinline__ void cpasync16(uint32_t s, const void* g) {
    asm volatile("cp.async.cg.shared.global [%0], [%1], 16;"
                 :: "r"(s), "l"(g) : "memory");
}
#define CP_COMMIT() asm volatile("cp.async.commit_group;" ::: "memory")
#define CP_WAIT2()  asm volatile("cp.async.wait_group 2;" ::: "memory")
#define CP_WAIT1()  asm volatile("cp.async.wait_group 1;" ::: "memory")
#define CP_WAIT0()  asm volatile("cp.async.wait_group 0;" ::: "memory")

__device__ __forceinline__ void split2(float x, float y,
                                       uint32_t& hi, uint32_t& lo) {
    __nv_bfloat16 hx = __float2bfloat16(x), hy = __float2bfloat16(y);
    __nv_bfloat16 lx = __float2bfloat16(x - __bfloat162float(hx));
    __nv_bfloat16 ly = __float2bfloat16(y - __bfloat162float(hy));
    __nv_bfloat162 H(hx, hy), L(lx, ly);
    hi = *(uint32_t*)&H; lo = *(uint32_t*)&L;
}

// ---------------------------------------------------------------------------
// fp32 -> bf16 hi/lo split (elementwise)
// ---------------------------------------------------------------------------
__global__ __launch_bounds__(256) void convert_split(
    const float* __restrict__ in, __nv_bfloat16* __restrict__ ohi,
    __nv_bfloat16* __restrict__ olo, int n4)
{
    int i = blockIdx.x * 256 + threadIdx.x;
    if (i >= n4) return;
    float4 v = ((const float4*)in)[i];
    uint32_t h0, l0, h1, l1;
    split2(v.x, v.y, h0, l0);
    split2(v.z, v.w, h1, l1);
    uint32_t* H = (uint32_t*)(ohi + (size_t)i * 4);
    uint32_t* L = (uint32_t*)(olo + (size_t)i * 4);
    H[0] = h0; H[1] = h1; L[0] = l0; L[1] = l1;
}

// fp32 [R][C] -> transposed bf16 hi/lo [C][R]
__global__ __launch_bounds__(256) void convert_trans(
    const float* __restrict__ in, __nv_bfloat16* __restrict__ ohi,
    __nv_bfloat16* __restrict__ olo, int R, int C)
{
    __shared__ float t[32][33];
    int bx = blockIdx.x * 32, by = blockIdx.y * 32;
    int lx = threadIdx.x & 31, ly = threadIdx.x >> 5;
#pragma unroll
    for (int i = 0; i < 4; i++)
        t[ly + i * 8][lx] = in[(size_t)(by + ly + i * 8) * C + bx + lx];
    __syncthreads();
#pragma unroll
    for (int i = 0; i < 4; i++) {
        float v = t[lx][ly + i * 8];
        __nv_bfloat16 h = __float2bfloat16(v);
        __nv_bfloat16 l = __float2bfloat16(v - __bfloat162float(h));
        size_t o = (size_t)(bx + ly + i * 8) * R + by + lx;
        ohi[o] = h; olo[o] = l;
    }
}

// ---------------------------------------------------------------------------
// Warp-MMA GEMM v4: C = A * B^T with hi/lo split, 3 products.
// CTA tile 128x128, K-chunk 64, 256 thr (8 warps, warp tile 32x64), 2-stage.
// NEW: product-major MMA ordering (16 independent chains between acc reuse)
// and register fragment double-buffering across kk (LDSM latency hidden).
// FUSE=true: fused LayerNorm+RoPE+split epilogue (head == warp n-tile).
// ---------------------------------------------------------------------------
#define STAGE 65536
#define GSMEM (2 * STAGE)

template <bool FUSE>
__global__ __launch_bounds__(256) void gemm_mma(
    const __nv_bfloat16* __restrict__ Ahi, const __nv_bfloat16* __restrict__ Alo,
    const __nv_bfloat16* __restrict__ Bhi, const __nv_bfloat16* __restrict__ Blo,
    float* __restrict__ C, int N, int K,
    const float* __restrict__ qg, const float* __restrict__ qbeta,
    const float* __restrict__ kg, const float* __restrict__ kbeta,
    const float* __restrict__ fcos, const float* __restrict__ fsin)
{
    extern __shared__ char dyn[];
    const int tid  = threadIdx.x;
    const int wid  = tid >> 5;
    const int lane = tid & 31;
    const int m0 = (wid & 3) * 32;
    const int n0 = (wid >> 2) * 64;
    const int bm = blockIdx.y * 128;
    const int bn = blockIdx.x * 128;
    const uint32_t sbase = smem_u32(dyn);

    float acc[2][8][4];
#pragma unroll
    for (int mi = 0; mi < 2; mi++)
#pragma unroll
        for (int ni = 0; ni < 8; ni++)
#pragma unroll
            for (int q = 0; q < 4; q++) acc[mi][ni][q] = 0.f;

    const int nk = K >> 6;

    auto issue = [&](int ck) {
        const int buf = ck & 1;
        const int k0 = ck * 64;
        const uint32_t sb = sbase + buf * STAGE;
#pragma unroll
        for (int i = 0; i < 4; i++) {
            int u = tid + i * 256;
            int row = u >> 3, c16 = u & 7;
            uint32_t so = SWZ128((uint32_t)(row * 128 + c16 * 16));
            size_t ga = (size_t)(bm + row) * K + k0 + c16 * 8;
            size_t gb = (size_t)(bn + row) * K + k0 + c16 * 8;
            cpasync16(sb +         so, Ahi + ga);
            cpasync16(sb + 16384 + so, Alo + ga);
            cpasync16(sb + 32768 + so, Bhi + gb);
            cpasync16(sb + 49152 + so, Blo + gb);
        }
        CP_COMMIT();
    };

    issue(0);
    const int lrow = lane & 15;
    const int lcb  = (lane >> 4) * 16;

    // double-buffered register fragments
    uint32_t fah[2][2][4], fal[2][2][4], fbh[2][4][4], fbl[2][4][4];

    auto load_frags = [&](uint32_t sb, int kk, int fb) {
#pragma unroll
        for (int mi = 0; mi < 2; mi++) {
            uint32_t off = SWZ128((uint32_t)((m0 + mi * 16 + lrow) * 128 +
                                             kk * 32 + lcb));
            ldm_x4(fah[fb][mi], sb + off);
            ldm_x4(fal[fb][mi], sb + 16384 + off);
        }
#pragma unroll
        for (int nj = 0; nj < 4; nj++) {
            uint32_t off = SWZ128((uint32_t)((n0 + nj * 16 + lrow) * 128 +
                                             kk * 32 + lcb));
            ldm_x4(fbh[fb][nj], sb + 32768 + off);
            ldm_x4(fbl[fb][nj], sb + 49152 + off);
        }
    };

    for (int ck = 0; ck < nk; ck++) {
        if (ck + 1 < nk) { issue(ck + 1); CP_WAIT1(); }
        else             { CP_WAIT0(); }
        __syncthreads();
        const uint32_t sb = sbase + (ck & 1) * STAGE;

        load_frags(sb, 0, 0);
#pragma unroll
        for (int kk = 0; kk < 4; kk++) {
            const int cur = kk & 1;
            if (kk < 3) load_frags(sb, kk + 1, cur ^ 1);
            // product-major: 16 independent MMAs between reuse of any acc
#pragma unroll
            for (int p = 0; p < 3; p++) {
#pragma unroll
                for (int mi = 0; mi < 2; mi++)
#pragma unroll
                    for (int ni = 0; ni < 8; ni++) {
                        const uint32_t* a = (p == 2) ? fal[cur][mi]
                                                     : fah[cur][mi];
                        const uint32_t* bf = (p == 1) ? fbl[cur][ni >> 1]
                                                      : fbh[cur][ni >> 1];
                        uint32_t b0 = (ni & 1) ? bf[1] : bf[0];
                        uint32_t b1 = (ni & 1) ? bf[3] : bf[2];
                        mma_bf16(acc[mi][ni], a, b0, b1);
                    }
            }
        }
        __syncthreads();
    }

    // ---------------- epilogue ----------------
    const int g = bn + n0;          // head-aligned column base (multiple of 64)
    const int hh = g >> 6;          // head index (Q:0-31, K:32-39, V:40-47)
    bool plain = !FUSE || (hh >= 40);

    if (plain) {
#pragma unroll
        for (int mi = 0; mi < 2; mi++) {
            int r0 = bm + m0 + mi * 16 + (lane >> 2);
#pragma unroll
            for (int ni = 0; ni < 8; ni++) {
                int c = g + ni * 8 + (lane & 3) * 2;
                *(float2*)&C[(size_t)r0 * N + c] =
                    make_float2(acc[mi][ni][0], acc[mi][ni][1]);
                *(float2*)&C[(size_t)(r0 + 8) * N + c] =
                    make_float2(acc[mi][ni][2], acc[mi][ni][3]);
            }
        }
    } else {
        const bool isQ = (hh < 32);
        const float* gam = isQ ? qg : kg;
        const float* bet = isQ ? qbeta : kbeta;
        const float scl = isQ ? 0.125f : 1.f;
        __nv_bfloat16* dh = isQ ? g_qh : g_kh;
        __nv_bfloat16* dl = isQ ? g_ql : g_kl;
        const int hloc = isQ ? hh : hh - 32;
        const int nheads = isQ ? NH_ : NKVH;

#pragma unroll
        for (int mi = 0; mi < 2; mi++) {
            // LayerNorm stats for the two rows this thread touches
            float s0 = 0.f, q0 = 0.f, s1 = 0.f, q1 = 0.f;
#pragma unroll
            for (int ni = 0; ni < 8; ni++) {
                s0 += acc[mi][ni][0] + acc[mi][ni][1];
                q0 += acc[mi][ni][0] * acc[mi][ni][0] +
                      acc[mi][ni][1] * acc[mi][ni][1];
                s1 += acc[mi][ni][2] + acc[mi][ni][3];
                q1 += acc[mi][ni][2] * acc[mi][ni][2] +
                      acc[mi][ni][3] * acc[mi][ni][3];
            }
#pragma unroll
            for (int off = 1; off <= 2; off <<= 1) {
                s0 += __shfl_xor_sync(0xffffffffu, s0, off);
                q0 += __shfl_xor_sync(0xffffffffu, q0, off);
                s1 += __shfl_xor_sync(0xffffffffu, s1, off);
                q1 += __shfl_xor_sync(0xffffffffu, q1, off);
            }
            float mu0 = s0 * (1.f / 64.f);
            float rs0 = rsqrtf(q0 * (1.f / 64.f) - mu0 * mu0 + EPS_);
            float mu1 = s1 * (1.f / 64.f);
            float rs1 = rsqrtf(q1 * (1.f / 64.f) - mu1 * mu1 + EPS_);

            int r0g = bm + m0 + mi * 16 + (lane >> 2);
            int r1g = r0g + 8;
            int b0 = r0g >> 11, si0 = r0g & (S_ - 1);
            int b1 = r1g >> 11, si1 = r1g & (S_ - 1);
            size_t base0 = ((size_t)(b0 * nheads + hloc) * S_ + si0) * 64;
            size_t base1 = ((size_t)(b1 * nheads + hloc) * S_ + si1) * 64;

#pragma unroll
            for (int ni = 0; ni < 8; ni++) {
                int cc = ni * 8 + (lane & 3) * 2;
                float gm0 = gam[cc], gm1 = gam[cc + 1];
                float bt0 = bet[cc], bt1 = bet[cc + 1];
                int f = cc >> 1;
                {   // row r0g
                    float xr = (acc[mi][ni][0] - mu0) * rs0 * gm0 + bt0;
                    float xi = (acc[mi][ni][1] - mu0) * rs0 * gm1 + bt1;
                    float c_ = fcos[si0 * 32 + f], sn = fsin[si0 * 32 + f];
                    uint32_t hi, lo;
                    split2((xr * c_ - xi * sn) * scl,
                           (xr * sn + xi * c_) * scl, hi, lo);
                    *(uint32_t*)(dh + base0 + cc) = hi;
                    *(uint32_t*)(dl + base0 + cc) = lo;
                }
                {   // row r0g + 8
                    float xr = (acc[mi][ni][2] - mu1) * rs1 * gm0 + bt0;
                    float xi = (acc[mi][ni][3] - mu1) * rs1 * gm1 + bt1;
                    float c_ = fcos[si1 * 32 + f], sn = fsin[si1 * 32 + f];
                    uint32_t hi, lo;
                    split2((xr * c_ - xi * sn) * scl,
                           (xr * sn + xi * c_) * scl, hi, lo);
                    *(uint32_t*)(dh + base1 + cc) = hi;
                    *(uint32_t*)(dl + base1 + cc) = lo;
                }
            }
        }
    }
}

// ---------------------------------------------------------------------------
// V: fp32 [b][s][kvh*64+d] -> bf16 hi/lo transposed [b*8+kvh][d][s]
// ---------------------------------------------------------------------------
__global__ __launch_bounds__(256) void vtrans_kernel()
{
    __shared__ float t[32][33];
    int s0 = blockIdx.x * 32;
    int d0 = blockIdx.y * 32;
    int bz = blockIdx.z;
    int b = bz >> 3, kvh = bz & 7;
    int lx = threadIdx.x & 31, ly = threadIdx.x >> 5;
#pragma unroll
    for (int i = 0; i < 4; i++)
        t[ly + i * 8][lx] =
            g_qkv[(size_t)(b * S_ + s0 + ly + i * 8) * QKVO + VOFF + kvh * 64 + d0 + lx];
    __syncthreads();
#pragma unroll
    for (int i = 0; i < 4; i++) {
        float v = t[lx][ly + i * 8];
        __nv_bfloat16 h = __float2bfloat16(v);
        __nv_bfloat16 l = __float2bfloat16(v - __bfloat162float(h));
        size_t o = ((size_t)bz * 64 + d0 + ly + i * 8) * S_ + s0 + lx;
        g_vh[o] = h; g_vl[o] = l;
    }
}

// ---------------------------------------------------------------------------
// Tensor-core flash attention: 256 thr / 8 warps, Q tile 128 (16 rows/warp),
// K tile 64, 3-stage cp.async ring. Product-major MMA ordering with hoisted
// B-fragment loads (same RAW-chain fix as the GEMM).
// Writes output directly as bf16 hi/lo splits into gemm2's A buffers.
// ---------------------------------------------------------------------------
#define ATT_STAGE 32768                        // Kh|Kl|Vh|Vl, 8 KB each
#define ATT_SMEM (3 * ATT_STAGE + 32768)       // + Qh|Ql (16 KB each) = 128 KB

__global__ __launch_bounds__(256) void attn_mma()
{
    extern __shared__ char dyn[];
    const int tid = threadIdx.x, wid = tid >> 5, lane = tid & 31;
    const int b = blockIdx.z, h = blockIdx.y;
    const int qb = (int)gridDim.x - 1 - (int)blockIdx.x;   // heavy first
    const int kvh = h >> 2;
    const uint32_t sb = smem_u32(dyn);
    const uint32_t qsm = sb + 3 * ATT_STAGE;

    const __nv_bfloat16* Qh = g_qh + ((size_t)(b * NH_ + h) * S_ + qb * 128) * 64;
    const __nv_bfloat16* Ql = g_ql + ((size_t)(b * NH_ + h) * S_ + qb * 128) * 64;
    const __nv_bfloat16* Kh = g_kh + (size_t)(b * NKVH + kvh) * S_ * 64;
    const __nv_bfloat16* Kl = g_kl + (size_t)(b * NKVH + kvh) * S_ * 64;
    const __nv_bfloat16* Vh = g_vh + (size_t)(b * NKVH + kvh) * 64 * S_;
    const __nv_bfloat16* Vl = g_vl + (size_t)(b * NKVH + kvh) * 64 * S_;

    const int nkb = 2 * qb + 2;

    auto issueKV = [&](int kb) {
        uint32_t st = sb + (kb % 3) * ATT_STAGE;
        const __nv_bfloat16* kh = Kh + (size_t)kb * 64 * 64;
        const __nv_bfloat16* kl = Kl + (size_t)kb * 64 * 64;
        const __nv_bfloat16* vh = Vh + kb * 64;
        const __nv_bfloat16* vl = Vl + kb * 64;
#pragma unroll
        for (int i = 0; i < 2; i++) {
            int u = tid + i * 256;
            int row = u >> 3, c16 = u & 7;
            uint32_t so = SWZ128((uint32_t)(row * 128 + c16 * 16));
            cpasync16(st +         so, kh + row * 64 + c16 * 8);
            cpasync16(st +  8192 + so, kl + row * 64 + c16 * 8);
            cpasync16(st + 16384 + so, vh + (size_t)row * S_ + c16 * 8);
            cpasync16(st + 24576 + so, vl + (size_t)row * S_ + c16 * 8);
        }
        CP_COMMIT();
    };

    // Q tile loads (group 0, committed by issueKV(0))
#pragma unroll
    for (int i = 0; i < 4; i++) {
        int u = tid + i * 256;
        int row = u >> 3, c16 = u & 7;
        uint32_t so = SWZ128((uint32_t)(row * 128 + c16 * 16));
        cpasync16(qsm +         so, Qh + (size_t)row * 64 + c16 * 8);
        cpasync16(qsm + 16384 + so, Ql + (size_t)row * 64 + c16 * 8);
    }
    issueKV(0);
    if (nkb > 1) issueKV(1);

    const int lrow = lane & 15;
    const int lcb  = (lane >> 4) * 16;

    uint32_t qfh[4][4], qfl[4][4];
    float o[8][4];
#pragma unroll
    for (int j = 0; j < 8; j++)
#pragma unroll
        for (int c = 0; c < 4; c++) o[j][c] = 0.f;
    float m0 = -1e30f, m1 = -1e30f, l0 = 0.f, l1 = 0.f;

    for (int kb = 0; kb < nkb; kb++) {
        __syncthreads();                       // stage reuse guard
        if (kb + 2 < nkb) { issueKV(kb + 2); CP_WAIT2(); }
        else if (kb + 1 < nkb) { CP_WAIT1(); }
        else { CP_WAIT0(); }
        __syncthreads();                       // data visible to all

        if (kb == 0) {
#pragma unroll
            for (int kc = 0; kc < 4; kc++) {
                uint32_t off = SWZ128((uint32_t)((wid * 16 + lrow) * 128 +
                                                 kc * 32 + lcb));
                ldm_x4(qfh[kc], qsm + off);
                ldm_x4(qfl[kc], qsm + 16384 + off);
            }
        }

        const uint32_t st = sb + (kb % 3) * ATT_STAGE;
        const int wrow0 = qb * 128 + wid * 16;
        if (kb * 64 > wrow0 + 15) continue;    // fully masked for this warp

        // ---- S = Q K^T (3-product split, product-major MMA order) ----
        float sc[8][4];
#pragma unroll
        for (int j = 0; j < 8; j++)
#pragma unroll
            for (int c = 0; c < 4; c++) sc[j][c] = 0.f;
#pragma unroll
        for (int kc = 0; kc < 4; kc++) {
            uint32_t bh[4][4], bl[4][4];
#pragma unroll
            for (int nj = 0; nj < 4; nj++) {
                uint32_t off = SWZ128((uint32_t)((nj * 16 + lrow) * 128 +
                                                 kc * 32 + lcb));
                ldm_x4(bh[nj], st + off);
                ldm_x4(bl[nj], st + 8192 + off);
            }
#pragma unroll
            for (int p = 0; p < 3; p++)
#pragma unroll
                for (int ni = 0; ni < 8; ni++) {
                    const uint32_t* a = (p == 2) ? qfl[kc] : qfh[kc];
                    const uint32_t* bf = (p == 1) ? bl[ni >> 1] : bh[ni >> 1];
                    uint32_t b0 = (ni & 1) ? bf[1] : bf[0];
                    uint32_t b1 = (ni & 1) ? bf[3] : bf[2];
                    mma_bf16(sc[ni], a, b0, b1);
                }
        }

        // ---- causal mask ----
        const int gr0 = wrow0 + (lane >> 2);
        if (kb * 64 + 63 > wrow0) {
#pragma unroll
            for (int j = 0; j < 8; j++) {
                int cb = kb * 64 + j * 8 + (lane & 3) * 2;
                if (cb     > gr0)     sc[j][0] = -1e30f;
                if (cb + 1 > gr0)     sc[j][1] = -1e30f;
                if (cb     > gr0 + 8) sc[j][2] = -1e30f;
                if (cb + 1 > gr0 + 8) sc[j][3] = -1e30f;
            }
        }

        // ---- online softmax (fp32, quad reductions) ----
        float mt0 = -1e30f, mt1 = -1e30f;
#pragma unroll
        for (int j = 0; j < 8; j++) {
            mt0 = fmaxf(mt0, fmaxf(sc[j][0], sc[j][1]));
            mt1 = fmaxf(mt1, fmaxf(sc[j][2], sc[j][3]));
        }
#pragma unroll
        for (int off = 1; off <= 2; off <<= 1) {
            mt0 = fmaxf(mt0, __shfl_xor_sync(0xffffffffu, mt0, off));
            mt1 = fmaxf(mt1, __shfl_xor_sync(0xffffffffu, mt1, off));
        }
        float mn0 = fmaxf(m0, mt0), mn1 = fmaxf(m1, mt1);
        float cr0 = __expf(m0 - mn0), cr1 = __expf(m1 - mn1);
        float rs0 = 0.f, rs1 = 0.f;
#pragma unroll
        for (int j = 0; j < 8; j++) {
            sc[j][0] = __expf(sc[j][0] - mn0);
            sc[j][1] = __expf(sc[j][1] - mn0);
            sc[j][2] = __expf(sc[j][2] - mn1);
            sc[j][3] = __expf(sc[j][3] - mn1);
            rs0 += sc[j][0] + sc[j][1];
            rs1 += sc[j][2] + sc[j][3];
        }
#pragma unroll
        for (int off = 1; off <= 2; off <<= 1) {
            rs0 += __shfl_xor_sync(0xffffffffu, rs0, off);
            rs1 += __shfl_xor_sync(0xffffffffu, rs1, off);
        }
        l0 = l0 * cr0 + rs0; l1 = l1 * cr1 + rs1;
        m0 = mn0; m1 = mn1;
#pragma unroll
        for (int j = 0; j < 8; j++) {
            o[j][0] *= cr0; o[j][1] *= cr0;
            o[j][2] *= cr1; o[j][3] *= cr1;
        }

        // ---- PV: split P, hoisted V frags, product-major mma ----
#pragma unroll
        for (int t = 0; t < 4; t++) {
            uint32_t aph[4], apl[4];
            split2(sc[2 * t][0],     sc[2 * t][1],     aph[0], apl[0]);
            split2(sc[2 * t][2],     sc[2 * t][3],     aph[1], apl[1]);
            split2(sc[2 * t + 1][0], sc[2 * t + 1][1], aph[2], apl[2]);
            split2(sc[2 * t + 1][2], sc[2 * t + 1][3], aph[3], apl[3]);
            uint32_t vh[4][4], vl[4][4];
#pragma unroll
            for (int nj = 0; nj < 4; nj++) {
                uint32_t off = SWZ128((uint32_t)((nj * 16 + lrow) * 128 +
                                                 t * 32 + lcb));
                ldm_x4(vh[nj], st + 16384 + off);
                ldm_x4(vl[nj], st + 24576 + off);
            }
#pragma unroll
            for (int p = 0; p < 3; p++)
#pragma unroll
                for (int ni = 0; ni < 8; ni++) {
                    const uint32_t* a = (p == 2) ? apl : aph;
                    const uint32_t* bf = (p == 1) ? vl[ni >> 1] : vh[ni >> 1];
                    uint32_t b0 = (ni & 1) ? bf[1] : bf[0];
                    uint32_t b1 = (ni & 1) ? bf[3] : bf[2];
                    mma_bf16(o[ni], a, b0, b1);
                }
        }
    }

    // ---- epilogue: write bf16 hi/lo splits directly into gemm2 A ----
    float il0 = 1.f / l0, il1 = 1.f / l1;
    int r0 = qb * 128 + wid * 16 + (lane >> 2);
    size_t row0 = (size_t)(b * S_ + r0) * DIM_;
    size_t row1 = row0 + (size_t)8 * DIM_;
    int colbase = h * 64 + (lane & 3) * 2;
#pragma unroll
    for (int j = 0; j < 8; j++) {
        uint32_t h0, lo0, h1, lo1;
        split2(o[j][0] * il0, o[j][1] * il0, h0, lo0);
        split2(o[j][2] * il1, o[j][3] * il1, h1, lo1);
        int c = colbase + j * 8;
        *(uint32_t*)(g_ahi + row0 + c) = h0;
        *(uint32_t*)(g_alo + row0 + c) = lo0;
        *(uint32_t*)(g_ahi + row1 + c) = h1;
        *(uint32_t*)(g_alo + row1 + c) = lo1;
    }
}

// ---------------------------------------------------------------------------
extern "C" void kernel_launch(void* const* d_in, const int* in_sizes, int n_in,
                              void* d_out, int out_size)
{
    const float* x     = (const float*)d_in[0];
    const float* wqkv  = (const float*)d_in[1];
    const float* wo    = (const float*)d_in[2];
    const float* q_g   = (const float*)d_in[3];
    const float* q_b   = (const float*)d_in[4];
    const float* k_g   = (const float*)d_in[5];
    const float* k_b   = (const float*)d_in[6];
    const float* fcos  = (const float*)d_in[7];
    const float* fsin  = (const float*)d_in[8];
    float* out = (float*)d_out;

    float* qkv_p = nullptr;
    __nv_bfloat16 *ahi, *alo, *bhi, *blo;
    cudaGetSymbolAddress((void**)&qkv_p, g_qkv);
    cudaGetSymbolAddress((void**)&ahi, g_ahi);
    cudaGetSymbolAddress((void**)&alo, g_alo);
    cudaGetSymbolAddress((void**)&bhi, g_bhi);
    cudaGetSymbolAddress((void**)&blo, g_blo);

    cudaFuncSetAttribute(gemm_mma<true>,
                         cudaFuncAttributeMaxDynamicSharedMemorySize, GSMEM);
    cudaFuncSetAttribute(gemm_mma<false>,
                         cudaFuncAttributeMaxDynamicSharedMemorySize, GSMEM);
    cudaFuncSetAttribute(attn_mma,
                         cudaFuncAttributeMaxDynamicSharedMemorySize, ATT_SMEM);

    // 1) split x (1 launch) and wqkv (2 launches -> gemm1 is launch #3 for ncu)
    {
        int n4 = MTOT * DIM_ / 4;
        convert_split<<<(n4 + 255) / 256, 256>>>(x, ahi, alo, n4);
        int half = QKVO * DIM_ / 2;
        int h4 = half / 4;
        convert_split<<<(h4 + 255) / 256, 256>>>(wqkv, bhi, blo, h4);
        convert_split<<<(h4 + 255) / 256, 256>>>(wqkv + half, bhi + half,
                                                 blo + half, h4);
    }

    // 2) QKV projection + fused LayerNorm/RoPE/split epilogue (launch #3)
    {
        dim3 grid(QKVO / 128, MTOT / 128);
        gemm_mma<true><<<grid, 256, GSMEM>>>(ahi, alo, bhi, blo, qkv_p,
                                             QKVO, DIM_, q_g, q_b, k_g, k_b,
                                             fcos, fsin);
    }

    // 3) V transpose/split
    {
        dim3 vg(S_ / 32, 2, B_ * NKVH);
        vtrans_kernel<<<vg, 256>>>();
    }

    // 4) Tensor-core flash attention (writes gemm2 A splits directly)
    {
        dim3 grid(S_ / 128, NH_, B_);
        attn_mma<<<grid, 256, ATT_SMEM>>>();
    }

    // 5) transpose+split wo -> [d][f]
    {
        dim3 tg(DIM_ / 32, DIM_ / 32);
        convert_trans<<<tg, 256>>>(wo, bhi, blo, DIM_, DIM_);
    }

    // 6) Output projection (tensor cores)
    {
        dim3 grid(DIM_ / 128, MTOT / 128);
        gemm_mma<false><<<grid, 256, GSMEM>>>(ahi, alo, bhi, blo, out,
                                              DIM_, DIM_, nullptr, nullptr,
                                              nullptr, nullptr, nullptr, nullptr);
    }
}

// round 16
// speedup vs baseline: 1.0226x; 1.0041x over previous
#include <cuda_runtime.h>
#include <cuda_bf16.h>
#include <math.h>
#include <stdint.h>

// Problem constants
#define B_   2
#define S_   2048
#define DIM_ 2048
#define NH_  32
#define NKVH 8
#define QKVO 3072          // (32 + 2*8) * 64
#define KOFF 2048
#define VOFF 2560
#define EPS_ 1e-5f
#define MTOT (B_ * S_)     // 4096

// Scratch (device globals — no allocation allowed)
__device__ float g_qkv[(size_t)B_ * S_ * QKVO];                  // V region used
__device__ __nv_bfloat16 g_ahi[(size_t)MTOT * DIM_];
__device__ __nv_bfloat16 g_alo[(size_t)MTOT * DIM_];
__device__ __nv_bfloat16 g_bhi[(size_t)QKVO * DIM_];
__device__ __nv_bfloat16 g_blo[(size_t)QKVO * DIM_];
// attention operand splits
__device__ __nv_bfloat16 g_qh[(size_t)B_ * NH_ * S_ * 64];
__device__ __nv_bfloat16 g_ql[(size_t)B_ * NH_ * S_ * 64];
__device__ __nv_bfloat16 g_kh[(size_t)B_ * NKVH * S_ * 64];
__device__ __nv_bfloat16 g_kl[(size_t)B_ * NKVH * S_ * 64];
__device__ __nv_bfloat16 g_vh[(size_t)B_ * NKVH * 64 * S_];      // [d][s]
__device__ __nv_bfloat16 g_vl[(size_t)B_ * NKVH * 64 * S_];

// ---------------------------------------------------------------------------
// PTX helpers (sm_103-safe)
// ---------------------------------------------------------------------------
__device__ __forceinline__ uint32_t smem_u32(const void* p) {
    uint32_t a;
    asm("{ .reg .u64 t; cvta.to.shared.u64 t, %1; cvt.u32.u64 %0, t; }"
        : "=r"(a) : "l"(p));
    return a;
}
#define SWZ128(o) ((o) ^ (((o) >> 3) & 0x70))

__device__ __forceinline__ void ldm_x4(uint32_t* r, uint32_t addr) {
    asm volatile("ldmatrix.sync.aligned.m8n8.x4.shared.b16 {%0,%1,%2,%3}, [%4];"
                 : "=r"(r[0]), "=r"(r[1]), "=r"(r[2]), "=r"(r[3]) : "r"(addr));
}
__device__ __forceinline__ void mma_bf16(float* c, const uint32_t* a,
                                         uint32_t b0, uint32_t b1) {
    asm volatile(
        "mma.sync.aligned.m16n8k16.row.col.f32.bf16.bf16.f32 "
        "{%0,%1,%2,%3}, {%4,%5,%6,%7}, {%8,%9}, {%0,%1,%2,%3};"
        : "+f"(c[0]), "+f"(c[1]), "+f"(c[2]), "+f"(c[3])
        : "r"(a[0]), "r"(a[1]), "r"(a[2]), "r"(a[3]), "r"(b0), "r"(b1));
}
__device__ __forceinline__ void cpasync16(uint32_t s, const void* g) {
    asm volatile("cp.async.cg.shared.global [%0], [%1], 16;"
                 :: "r"(s), "l"(g) : "memory");
}
#define CP_COMMIT() asm volatile("cp.async.commit_group;" ::: "memory")
#define CP_WAIT2()  asm volatile("cp.async.wait_group 2;" ::: "memory")
#define CP_WAIT1()  asm volatile("cp.async.wait_group 1;" ::: "memory")
#define CP_WAIT0()  asm volatile("cp.async.wait_group 0;" ::: "memory")

__device__ __forceinline__ void split2(float x, float y,
                                       uint32_t& hi, uint32_t& lo) {
    __nv_bfloat16 hx = __float2bfloat16(x), hy = __float2bfloat16(y);
    __nv_bfloat16 lx = __float2bfloat16(x - __bfloat162float(hx));
    __nv_bfloat16 ly = __float2bfloat16(y - __bfloat162float(hy));
    __nv_bfloat162 H(hx, hy), L(lx, ly);
    hi = *(uint32_t*)&H; lo = *(uint32_t*)&L;
}

// ---------------------------------------------------------------------------
// fp32 -> bf16 hi/lo split (elementwise)
// ---------------------------------------------------------------------------
__global__ __launch_bounds__(256) void convert_split(
    const float* __restrict__ in, __nv_bfloat16* __restrict__ ohi,
    __nv_bfloat16* __restrict__ olo, int n4)
{
    int i = blockIdx.x * 256 + threadIdx.x;
    if (i >= n4) return;
    float4 v = ((const float4*)in)[i];
    uint32_t h0, l0, h1, l1;
    split2(v.x, v.y, h0, l0);
    split2(v.z, v.w, h1, l1);
    uint32_t* H = (uint32_t*)(ohi + (size_t)i * 4);
    uint32_t* L = (uint32_t*)(olo + (size_t)i * 4);
    H[0] = h0; H[1] = h1; L[0] = l0; L[1] = l1;
}

// fp32 [R][C] -> transposed bf16 hi/lo [C][R]
__global__ __launch_bounds__(256) void convert_trans(
    const float* __restrict__ in, __nv_bfloat16* __restrict__ ohi,
    __nv_bfloat16* __restrict__ olo, int R, int C)
{
    __shared__ float t[32][33];
    int bx = blockIdx.x * 32, by = blockIdx.y * 32;
    int lx = threadIdx.x & 31, ly = threadIdx.x >> 5;
#pragma unroll
    for (int i = 0; i < 4; i++)
        t[ly + i * 8][lx] = in[(size_t)(by + ly + i * 8) * C + bx + lx];
    __syncthreads();
#pragma unroll
    for (int i = 0; i < 4; i++) {
        float v = t[lx][ly + i * 8];
        __nv_bfloat16 h = __float2bfloat16(v);
        __nv_bfloat16 l = __float2bfloat16(v - __bfloat162float(h));
        size_t o = (size_t)(bx + ly + i * 8) * R + by + lx;
        ohi[o] = h; olo[o] = l;
    }
}

// ---------------------------------------------------------------------------
// Warp-MMA GEMM v5: C = A * B^T with hi/lo split, 3 products.
// CTA tile 256x128, K-chunk 64, 256 thr (8 warps, WARP TILE 64x64 -> 85 B of
// LDSM traffic per MMA instead of 128 -> smem-crossbar ceiling 55% -> ~82%).
// 2-stage cp.async ring (96 KB/stage). Product-major MMA order.
// FUSE=true: fused LayerNorm+RoPE+split epilogue (head == warp n-tile).
// ---------------------------------------------------------------------------
#define STAGE 98304          // Ahi 32K | Alo 32K | Bhi 16K | Blo 16K
#define GSMEM (2 * STAGE)    // 196608

template <bool FUSE>
__global__ __launch_bounds__(256) void gemm_mma(
    const __nv_bfloat16* __restrict__ Ahi, const __nv_bfloat16* __restrict__ Alo,
    const __nv_bfloat16* __restrict__ Bhi, const __nv_bfloat16* __restrict__ Blo,
    float* __restrict__ C, int N, int K,
    const float* __restrict__ qg, const float* __restrict__ qbeta,
    const float* __restrict__ kg, const float* __restrict__ kbeta,
    const float* __restrict__ fcos, const float* __restrict__ fsin)
{
    extern __shared__ char dyn[];
    const int tid  = threadIdx.x;
    const int wid  = tid >> 5;
    const int lane = tid & 31;
    const int m0 = (wid & 3) * 64;          // 4 m-warps x 64 rows
    const int n0 = (wid >> 2) * 64;         // 2 n-warps x 64 cols
    const int bm = blockIdx.y * 256;
    const int bn = blockIdx.x * 128;
    const uint32_t sbase = smem_u32(dyn);

    float acc[4][8][4];                     // 128 regs
#pragma unroll
    for (int mi = 0; mi < 4; mi++)
#pragma unroll
        for (int ni = 0; ni < 8; ni++)
#pragma unroll
            for (int q = 0; q < 4; q++) acc[mi][ni][q] = 0.f;

    const int nk = K >> 6;

    auto issue = [&](int ck) {
        const uint32_t sb = sbase + (ck & 1) * STAGE;
        const int k0 = ck * 64;
#pragma unroll
        for (int i = 0; i < 8; i++) {           // A: 256 rows
            int u = tid + i * 256;
            int row = u >> 3, c16 = u & 7;
            uint32_t so = SWZ128((uint32_t)(row * 128 + c16 * 16));
            size_t ga = (size_t)(bm + row) * K + k0 + c16 * 8;
            cpasync16(sb +         so, Ahi + ga);
            cpasync16(sb + 32768 + so, Alo + ga);
        }
#pragma unroll
        for (int i = 0; i < 4; i++) {           // B: 128 rows
            int u = tid + i * 256;
            int row = u >> 3, c16 = u & 7;
            uint32_t so = SWZ128((uint32_t)(row * 128 + c16 * 16));
            size_t gb = (size_t)(bn + row) * K + k0 + c16 * 8;
            cpasync16(sb + 65536 + so, Bhi + gb);
            cpasync16(sb + 81920 + so, Blo + gb);
        }
        CP_COMMIT();
    };

    issue(0);
    const int lrow = lane & 15;
    const int lcb  = (lane >> 4) * 16;

    for (int ck = 0; ck < nk; ck++) {
        if (ck + 1 < nk) { issue(ck + 1); CP_WAIT1(); }
        else             { CP_WAIT0(); }
        __syncthreads();
        const uint32_t sb = sbase + (ck & 1) * STAGE;

#pragma unroll
        for (int kk = 0; kk < 4; kk++) {
            uint32_t ah[4][4], al[4][4];
#pragma unroll
            for (int mi = 0; mi < 4; mi++) {
                uint32_t off = SWZ128((uint32_t)((m0 + mi * 16 + lrow) * 128 +
                                                 kk * 32 + lcb));
                ldm_x4(ah[mi], sb + off);
                ldm_x4(al[mi], sb + 32768 + off);
            }
#pragma unroll
            for (int njh = 0; njh < 2; njh++) {  // B frags in 2 halves (regs)
                uint32_t bh[2][4], bl[2][4];
#pragma unroll
                for (int nj = 0; nj < 2; nj++) {
                    uint32_t off = SWZ128((uint32_t)(
                        (n0 + (njh * 2 + nj) * 16 + lrow) * 128 +
                        kk * 32 + lcb));
                    ldm_x4(bh[nj], sb + 65536 + off);
                    ldm_x4(bl[nj], sb + 81920 + off);
                }
                // product-major: 16 independent accs between reuse
#pragma unroll
                for (int p = 0; p < 3; p++)
#pragma unroll
                    for (int mi = 0; mi < 4; mi++)
#pragma unroll
                        for (int nl = 0; nl < 4; nl++) {
                            const uint32_t* a = (p == 2) ? al[mi] : ah[mi];
                            const uint32_t* bf = (p == 1) ? bl[nl >> 1]
                                                          : bh[nl >> 1];
                            uint32_t b0 = (nl & 1) ? bf[1] : bf[0];
                            uint32_t b1 = (nl & 1) ? bf[3] : bf[2];
                            mma_bf16(acc[mi][njh * 4 + nl], a, b0, b1);
                        }
            }
        }
        __syncthreads();
    }

    // ---------------- epilogue ----------------
    const int g = bn + n0;          // head-aligned column base (multiple of 64)
    const int hh = g >> 6;          // head index (Q:0-31, K:32-39, V:40-47)
    bool plain = !FUSE || (hh >= 40);

    if (plain) {
#pragma unroll
        for (int mi = 0; mi < 4; mi++) {
            int r0 = bm + m0 + mi * 16 + (lane >> 2);
#pragma unroll
            for (int ni = 0; ni < 8; ni++) {
                int c = g + ni * 8 + (lane & 3) * 2;
                *(float2*)&C[(size_t)r0 * N + c] =
                    make_float2(acc[mi][ni][0], acc[mi][ni][1]);
                *(float2*)&C[(size_t)(r0 + 8) * N + c] =
                    make_float2(acc[mi][ni][2], acc[mi][ni][3]);
            }
        }
    } else {
        const bool isQ = (hh < 32);
        const float* gam = isQ ? qg : kg;
        const float* bet = isQ ? qbeta : kbeta;
        const float scl = isQ ? 0.125f : 1.f;
        __nv_bfloat16* dh = isQ ? g_qh : g_kh;
        __nv_bfloat16* dl = isQ ? g_ql : g_kl;
        const int hloc = isQ ? hh : hh - 32;
        const int nheads = isQ ? NH_ : NKVH;

#pragma unroll
        for (int mi = 0; mi < 4; mi++) {
            float s0 = 0.f, q0 = 0.f, s1 = 0.f, q1 = 0.f;
#pragma unroll
            for (int ni = 0; ni < 8; ni++) {
                s0 += acc[mi][ni][0] + acc[mi][ni][1];
                q0 += acc[mi][ni][0] * acc[mi][ni][0] +
                      acc[mi][ni][1] * acc[mi][ni][1];
                s1 += acc[mi][ni][2] + acc[mi][ni][3];
                q1 += acc[mi][ni][2] * acc[mi][ni][2] +
                      acc[mi][ni][3] * acc[mi][ni][3];
            }
#pragma unroll
            for (int off = 1; off <= 2; off <<= 1) {
                s0 += __shfl_xor_sync(0xffffffffu, s0, off);
                q0 += __shfl_xor_sync(0xffffffffu, q0, off);
                s1 += __shfl_xor_sync(0xffffffffu, s1, off);
                q1 += __shfl_xor_sync(0xffffffffu, q1, off);
            }
            float mu0 = s0 * (1.f / 64.f);
            float rs0 = rsqrtf(q0 * (1.f / 64.f) - mu0 * mu0 + EPS_);
            float mu1 = s1 * (1.f / 64.f);
            float rs1 = rsqrtf(q1 * (1.f / 64.f) - mu1 * mu1 + EPS_);

            int r0g = bm + m0 + mi * 16 + (lane >> 2);
            int r1g = r0g + 8;
            int b0 = r0g >> 11, si0 = r0g & (S_ - 1);
            int b1 = r1g >> 11, si1 = r1g & (S_ - 1);
            size_t base0 = ((size_t)(b0 * nheads + hloc) * S_ + si0) * 64;
            size_t base1 = ((size_t)(b1 * nheads + hloc) * S_ + si1) * 64;

#pragma unroll
            for (int ni = 0; ni < 8; ni++) {
                int cc = ni * 8 + (lane & 3) * 2;
                float gm0 = gam[cc], gm1 = gam[cc + 1];
                float bt0 = bet[cc], bt1 = bet[cc + 1];
                int f = cc >> 1;
                {   // row r0g
                    float xr = (acc[mi][ni][0] - mu0) * rs0 * gm0 + bt0;
                    float xi = (acc[mi][ni][1] - mu0) * rs0 * gm1 + bt1;
                    float c_ = fcos[si0 * 32 + f], sn = fsin[si0 * 32 + f];
                    uint32_t hi, lo;
                    split2((xr * c_ - xi * sn) * scl,
                           (xr * sn + xi * c_) * scl, hi, lo);
                    *(uint32_t*)(dh + base0 + cc) = hi;
                    *(uint32_t*)(dl + base0 + cc) = lo;
                }
                {   // row r0g + 8
                    float xr = (acc[mi][ni][2] - mu1) * rs1 * gm0 + bt0;
                    float xi = (acc[mi][ni][3] - mu1) * rs1 * gm1 + bt1;
                    float c_ = fcos[si1 * 32 + f], sn = fsin[si1 * 32 + f];
                    uint32_t hi, lo;
                    split2((xr * c_ - xi * sn) * scl,
                           (xr * sn + xi * c_) * scl, hi, lo);
                    *(uint32_t*)(dh + base1 + cc) = hi;
                    *(uint32_t*)(dl + base1 + cc) = lo;
                }
            }
        }
    }
}

// ---------------------------------------------------------------------------
// V: fp32 [b][s][kvh*64+d] -> bf16 hi/lo transposed [b*8+kvh][d][s]
// ---------------------------------------------------------------------------
__global__ __launch_bounds__(256) void vtrans_kernel()
{
    __shared__ float t[32][33];
    int s0 = blockIdx.x * 32;
    int d0 = blockIdx.y * 32;
    int bz = blockIdx.z;
    int b = bz >> 3, kvh = bz & 7;
    int lx = threadIdx.x & 31, ly = threadIdx.x >> 5;
#pragma unroll
    for (int i = 0; i < 4; i++)
        t[ly + i * 8][lx] =
            g_qkv[(size_t)(b * S_ + s0 + ly + i * 8) * QKVO + VOFF + kvh * 64 + d0 + lx];
    __syncthreads();
#pragma unroll
    for (int i = 0; i < 4; i++) {
        float v = t[lx][ly + i * 8];
        __nv_bfloat16 h = __float2bfloat16(v);
        __nv_bfloat16 l = __float2bfloat16(v - __bfloat162float(h));
        size_t o = ((size_t)bz * 64 + d0 + ly + i * 8) * S_ + s0 + lx;
        g_vh[o] = h; g_vl[o] = l;
    }
}

// ---------------------------------------------------------------------------
// Tensor-core flash attention v6: 256 thr / 8 warps, Q tile 256 (32 rows per
// warp -> warp tile 32x64 -> 106 B LDSM/MMA instead of 170), K tile 64,
// 3-stage cp.async ring, product-major MMA order with hoisted frags.
// Q fragments reloaded from smem per kc (keeps regs under control).
// Writes output directly as bf16 hi/lo splits into gemm2's A buffers.
// ---------------------------------------------------------------------------
#define ATT_STAGE 32768                        // Kh|Kl|Vh|Vl, 8 KB each
#define ATT_SMEM (3 * ATT_STAGE + 65536)       // + Qh|Ql (32 KB each) = 160 KB

__global__ __launch_bounds__(256) void attn_mma()
{
    extern __shared__ char dyn[];
    const int tid = threadIdx.x, wid = tid >> 5, lane = tid & 31;
    const int b = blockIdx.z, h = blockIdx.y;
    const int qb = (int)gridDim.x - 1 - (int)blockIdx.x;   // heavy first
    const int kvh = h >> 2;
    const uint32_t sb = smem_u32(dyn);
    const uint32_t qsm = sb + 3 * ATT_STAGE;

    const __nv_bfloat16* Qh = g_qh + ((size_t)(b * NH_ + h) * S_ + qb * 256) * 64;
    const __nv_bfloat16* Ql = g_ql + ((size_t)(b * NH_ + h) * S_ + qb * 256) * 64;
    const __nv_bfloat16* Kh = g_kh + (size_t)(b * NKVH + kvh) * S_ * 64;
    const __nv_bfloat16* Kl = g_kl + (size_t)(b * NKVH + kvh) * S_ * 64;
    const __nv_bfloat16* Vh = g_vh + (size_t)(b * NKVH + kvh) * 64 * S_;
    const __nv_bfloat16* Vl = g_vl + (size_t)(b * NKVH + kvh) * 64 * S_;

    const int nkb = 4 * qb + 4;

    auto issueKV = [&](int kb) {
        uint32_t st = sb + (kb % 3) * ATT_STAGE;
        const __nv_bfloat16* kh = Kh + (size_t)kb * 64 * 64;
        const __nv_bfloat16* kl = Kl + (size_t)kb * 64 * 64;
        const __nv_bfloat16* vh = Vh + kb * 64;
        const __nv_bfloat16* vl = Vl + kb * 64;
#pragma unroll
        for (int i = 0; i < 2; i++) {
            int u = tid + i * 256;
            int row = u >> 3, c16 = u & 7;
            uint32_t so = SWZ128((uint32_t)(row * 128 + c16 * 16));
            cpasync16(st +         so, kh + row * 64 + c16 * 8);
            cpasync16(st +  8192 + so, kl + row * 64 + c16 * 8);
            cpasync16(st + 16384 + so, vh + (size_t)row * S_ + c16 * 8);
            cpasync16(st + 24576 + so, vl + (size_t)row * S_ + c16 * 8);
        }
        CP_COMMIT();
    };

    // Q tile loads (256 rows; committed with issueKV(0) in group 0)
#pragma unroll
    for (int i = 0; i < 8; i++) {
        int u = tid + i * 256;
        int row = u >> 3, c16 = u & 7;
        uint32_t so = SWZ128((uint32_t)(row * 128 + c16 * 16));
        cpasync16(qsm +         so, Qh + (size_t)row * 64 + c16 * 8);
        cpasync16(qsm + 32768 + so, Ql + (size_t)row * 64 + c16 * 8);
    }
    issueKV(0);
    if (nkb > 1) issueKV(1);

    const int lrow = lane & 15;
    const int lcb  = (lane >> 4) * 16;
    const int wrow0 = qb * 256 + wid * 32;

    float o[2][8][4];
    float m_[2][2], l_[2][2];
#pragma unroll
    for (int mi = 0; mi < 2; mi++) {
        m_[mi][0] = -1e30f; m_[mi][1] = -1e30f;
        l_[mi][0] = 0.f;    l_[mi][1] = 0.f;
#pragma unroll
        for (int j = 0; j < 8; j++)
#pragma unroll
            for (int c = 0; c < 4; c++) o[mi][j][c] = 0.f;
    }

    for (int kb = 0; kb < nkb; kb++) {
        __syncthreads();                       // stage reuse guard
        if (kb + 2 < nkb) { issueKV(kb + 2); CP_WAIT2(); }
        else if (kb + 1 < nkb) { CP_WAIT1(); }
        else { CP_WAIT0(); }
        __syncthreads();                       // data visible to all

        const uint32_t st = sb + (kb % 3) * ATT_STAGE;
        if (kb * 64 > wrow0 + 31) continue;    // fully masked for this warp

        // ---- S = Q K^T (3-product split, product-major) ----
        float sc[2][8][4];
#pragma unroll
        for (int mi = 0; mi < 2; mi++)
#pragma unroll
            for (int j = 0; j < 8; j++)
#pragma unroll
                for (int c = 0; c < 4; c++) sc[mi][j][c] = 0.f;
#pragma unroll
        for (int kc = 0; kc < 4; kc++) {
            uint32_t qfh[2][4], qfl[2][4];
#pragma unroll
            for (int mi = 0; mi < 2; mi++) {
                uint32_t off = SWZ128((uint32_t)((wid * 32 + mi * 16 + lrow) * 128 +
                                                 kc * 32 + lcb));
                ldm_x4(qfh[mi], qsm + off);
                ldm_x4(qfl[mi], qsm + 32768 + off);
            }
            uint32_t bh[4][4], bl[4][4];
#pragma unroll
            for (int nj = 0; nj < 4; nj++) {
                uint32_t off = SWZ128((uint32_t)((nj * 16 + lrow) * 128 +
                                                 kc * 32 + lcb));
                ldm_x4(bh[nj], st + off);
                ldm_x4(bl[nj], st + 8192 + off);
            }
#pragma unroll
            for (int p = 0; p < 3; p++)
#pragma unroll
                for (int mi = 0; mi < 2; mi++)
#pragma unroll
                    for (int ni = 0; ni < 8; ni++) {
                        const uint32_t* a = (p == 2) ? qfl[mi] : qfh[mi];
                        const uint32_t* bf = (p == 1) ? bl[ni >> 1]
                                                      : bh[ni >> 1];
                        uint32_t b0 = (ni & 1) ? bf[1] : bf[0];
                        uint32_t b1 = (ni & 1) ? bf[3] : bf[2];
                        mma_bf16(sc[mi][ni], a, b0, b1);
                    }
        }

        // ---- causal mask ----
        if (kb * 64 + 63 > wrow0) {
#pragma unroll
            for (int mi = 0; mi < 2; mi++) {
                int gr0 = wrow0 + mi * 16 + (lane >> 2);
#pragma unroll
                for (int j = 0; j < 8; j++) {
                    int cb = kb * 64 + j * 8 + (lane & 3) * 2;
                    if (cb     > gr0)     sc[mi][j][0] = -1e30f;
                    if (cb + 1 > gr0)     sc[mi][j][1] = -1e30f;
                    if (cb     > gr0 + 8) sc[mi][j][2] = -1e30f;
                    if (cb + 1 > gr0 + 8) sc[mi][j][3] = -1e30f;
                }
            }
        }

        // ---- online softmax (fp32, quad reductions) ----
#pragma unroll
        for (int mi = 0; mi < 2; mi++) {
            float mt0 = -1e30f, mt1 = -1e30f;
#pragma unroll
            for (int j = 0; j < 8; j++) {
                mt0 = fmaxf(mt0, fmaxf(sc[mi][j][0], sc[mi][j][1]));
                mt1 = fmaxf(mt1, fmaxf(sc[mi][j][2], sc[mi][j][3]));
            }
#pragma unroll
            for (int off = 1; off <= 2; off <<= 1) {
                mt0 = fmaxf(mt0, __shfl_xor_sync(0xffffffffu, mt0, off));
                mt1 = fmaxf(mt1, __shfl_xor_sync(0xffffffffu, mt1, off));
            }
            float mn0 = fmaxf(m_[mi][0], mt0), mn1 = fmaxf(m_[mi][1], mt1);
            float cr0 = __expf(m_[mi][0] - mn0), cr1 = __expf(m_[mi][1] - mn1);
            float rs0 = 0.f, rs1 = 0.f;
#pragma unroll
            for (int j = 0; j < 8; j++) {
                sc[mi][j][0] = __expf(sc[mi][j][0] - mn0);
                sc[mi][j][1] = __expf(sc[mi][j][1] - mn0);
                sc[mi][j][2] = __expf(sc[mi][j][2] - mn1);
                sc[mi][j][3] = __expf(sc[mi][j][3] - mn1);
                rs0 += sc[mi][j][0] + sc[mi][j][1];
                rs1 += sc[mi][j][2] + sc[mi][j][3];
            }
#pragma unroll
            for (int off = 1; off <= 2; off <<= 1) {
                rs0 += __shfl_xor_sync(0xffffffffu, rs0, off);
                rs1 += __shfl_xor_sync(0xffffffffu, rs1, off);
            }
            l_[mi][0] = l_[mi][0] * cr0 + rs0;
            l_[mi][1] = l_[mi][1] * cr1 + rs1;
            m_[mi][0] = mn0; m_[mi][1] = mn1;
#pragma unroll
            for (int j = 0; j < 8; j++) {
                o[mi][j][0] *= cr0; o[mi][j][1] *= cr0;
                o[mi][j][2] *= cr1; o[mi][j][3] *= cr1;
            }
        }

        // ---- PV: split P, hoisted V frags, product-major mma ----
#pragma unroll
        for (int t = 0; t < 4; t++) {
            uint32_t aph[2][4], apl[2][4];
#pragma unroll
            for (int mi = 0; mi < 2; mi++) {
                split2(sc[mi][2 * t][0],     sc[mi][2 * t][1],     aph[mi][0], apl[mi][0]);
                split2(sc[mi][2 * t][2],     sc[mi][2 * t][3],     aph[mi][1], apl[mi][1]);
                split2(sc[mi][2 * t + 1][0], sc[mi][2 * t + 1][1], aph[mi][2], apl[mi][2]);
                split2(sc[mi][2 * t + 1][2], sc[mi][2 * t + 1][3], aph[mi][3], apl[mi][3]);
            }
            uint32_t vh[4][4], vl[4][4];
#pragma unroll
            for (int nj = 0; nj < 4; nj++) {
                uint32_t off = SWZ128((uint32_t)((nj * 16 + lrow) * 128 +
                                                 t * 32 + lcb));
                ldm_x4(vh[nj], st + 16384 + off);
                ldm_x4(vl[nj], st + 24576 + off);
            }
#pragma unroll
            for (int p = 0; p < 3; p++)
#pragma unroll
                for (int mi = 0; mi < 2; mi++)
#pragma unroll
                    for (int ni = 0; ni < 8; ni++) {
                        const uint32_t* a = (p == 2) ? apl[mi] : aph[mi];
                        const uint32_t* bf = (p == 1) ? vl[ni >> 1]
                                                      : vh[ni >> 1];
                        uint32_t b0 = (ni & 1) ? bf[1] : bf[0];
                        uint32_t b1 = (ni & 1) ? bf[3] : bf[2];
                        mma_bf16(o[mi][ni], a, b0, b1);
                    }
        }
    }

    // ---- epilogue: write bf16 hi/lo splits directly into gemm2 A ----
#pragma unroll
    for (int mi = 0; mi < 2; mi++) {
        float il0 = 1.f / l_[mi][0], il1 = 1.f / l_[mi][1];
        int r0 = qb * 256 + wid * 32 + mi * 16 + (lane >> 2);
        size_t row0 = (size_t)(b * S_ + r0) * DIM_;
        size_t row1 = row0 + (size_t)8 * DIM_;
        int colbase = h * 64 + (lane & 3) * 2;
#pragma unroll
        for (int j = 0; j < 8; j++) {
            uint32_t h0, lo0, h1, lo1;
            split2(o[mi][j][0] * il0, o[mi][j][1] * il0, h0, lo0);
            split2(o[mi][j][2] * il1, o[mi][j][3] * il1, h1, lo1);
            int c = colbase + j * 8;
            *(uint32_t*)(g_ahi + row0 + c) = h0;
            *(uint32_t*)(g_alo + row0 + c) = lo0;
            *(uint32_t*)(g_ahi + row1 + c) = h1;
            *(uint32_t*)(g_alo + row1 + c) = lo1;
        }
    }
}

// ---------------------------------------------------------------------------
extern "C" void kernel_launch(void* const* d_in, const int* in_sizes, int n_in,
                              void* d_out, int out_size)
{
    const float* x     = (const float*)d_in[0];
    const float* wqkv  = (const float*)d_in[1];
    const float* wo    = (const float*)d_in[2];
    const float* q_g   = (const float*)d_in[3];
    const float* q_b   = (const float*)d_in[4];
    const float* k_g   = (const float*)d_in[5];
    const float* k_b   = (const float*)d_in[6];
    const float* fcos  = (const float*)d_in[7];
    const float* fsin  = (const float*)d_in[8];
    float* out = (float*)d_out;

    float* qkv_p = nullptr;
    __nv_bfloat16 *ahi, *alo, *bhi, *blo;
    cudaGetSymbolAddress((void**)&qkv_p, g_qkv);
    cudaGetSymbolAddress((void**)&ahi, g_ahi);
    cudaGetSymbolAddress((void**)&alo, g_alo);
    cudaGetSymbolAddress((void**)&bhi, g_bhi);
    cudaGetSymbolAddress((void**)&blo, g_blo);

    cudaFuncSetAttribute(gemm_mma<true>,
                         cudaFuncAttributeMaxDynamicSharedMemorySize, GSMEM);
    cudaFuncSetAttribute(gemm_mma<false>,
                         cudaFuncAttributeMaxDynamicSharedMemorySize, GSMEM);
    cudaFuncSetAttribute(attn_mma,
                         cudaFuncAttributeMaxDynamicSharedMemorySize, ATT_SMEM);

    // 1) split x (1 launch) and wqkv (2 launches -> gemm1 is launch #3 for ncu)
    {
        int n4 = MTOT * DIM_ / 4;
        convert_split<<<(n4 + 255) / 256, 256>>>(x, ahi, alo, n4);
        int half = QKVO * DIM_ / 2;
        int h4 = half / 4;
        convert_split<<<(h4 + 255) / 256, 256>>>(wqkv, bhi, blo, h4);
        convert_split<<<(h4 + 255) / 256, 256>>>(wqkv + half, bhi + half,
                                                 blo + half, h4);
    }

    // 2) QKV projection + fused LayerNorm/RoPE/split epilogue (launch #3)
    {
        dim3 grid(QKVO / 128, MTOT / 256);
        gemm_mma<true><<<grid, 256, GSMEM>>>(ahi, alo, bhi, blo, qkv_p,
                                             QKVO, DIM_, q_g, q_b, k_g, k_b,
                                             fcos, fsin);
    }

    // 3) V transpose/split
    {
        dim3 vg(S_ / 32, 2, B_ * NKVH);
        vtrans_kernel<<<vg, 256>>>();
    }

    // 4) Tensor-core flash attention (writes gemm2 A splits directly)
    {
        dim3 grid(S_ / 256, NH_, B_);
        attn_mma<<<grid, 256, ATT_SMEM>>>();
    }

    // 5) transpose+split wo -> [d][f]
    {
        dim3 tg(DIM_ / 32, DIM_ / 32);
        convert_trans<<<tg, 256>>>(wo, bhi, blo, DIM_, DIM_);
    }

    // 6) Output projection (tensor cores)
    {
        dim3 grid(DIM_ / 128, MTOT / 256);
        gemm_mma<false><<<grid, 256, GSMEM>>>(ahi, alo, bhi, blo, out,
                                              DIM_, DIM_, nullptr, nullptr,
                                              nullptr, nullptr, nullptr, nullptr);
    }
}